// round 4
// baseline (speedup 1.0000x reference)
#include <cuda_runtime.h>
#include <cstdint>

typedef unsigned long long ULL;

__device__ __forceinline__ ULL pack2(float lo, float hi) {
    ULL r; asm("mov.b64 %0, {%1, %2};" : "=l"(r) : "f"(lo), "f"(hi)); return r;
}
__device__ __forceinline__ void unpack2(ULL v, float& lo, float& hi) {
    asm("mov.b64 {%0, %1}, %2;" : "=f"(lo), "=f"(hi) : "l"(v));
}
__device__ __forceinline__ ULL fma2(ULL a, ULL b, ULL c) {
    ULL d; asm("fma.rn.f32x2 %0, %1, %2, %3;" : "=l"(d) : "l"(a), "l"(b), "l"(c)); return d;
}

#define NN 256

// ============================================================================
// Fused kernel: one block per node (b,j).
//   Phase A: Hsum[h] = sum_i relu(e[b,i,j,:]@W1 + b1)        (dominant GEMM)
//   Phase B: wsum[cd] = Hsum@W2 + 256*b2 + root  (W2 from L1-cached gmem)
//   Phase C: out[j,d] = sum_c x[j,c] * wsum[c*16+d]
// ============================================================================
__global__ __launch_bounds__(128, 6)
void k_fused(const float* __restrict__ x,
             const float* __restrict__ edge,
             const float* __restrict__ W1,
             const float* __restrict__ b1,
             const float* __restrict__ W2,
             const float* __restrict__ b2,
             const float* __restrict__ root,
             float* __restrict__ out) {
    __shared__ float es[2][64 * 18];   // e rows duplicated, pitch 18
    __shared__ float w1s[512];
    __shared__ float hsum[64];
    __shared__ ULL   hs2[64];          // hsum splatted for fma2
    __shared__ float wpart[2][256];    // h-half partials of Hsum@W2
    __shared__ float wsf[256];
    __shared__ float xs[16];

    const int t  = threadIdx.x;
    const int bx = blockIdx.x;         // node id = b*256 + j
    const int j  = bx & 255;
    const int b  = bx >> 8;

    if (t < 64) hsum[t] = 0.f;
    #pragma unroll
    for (int r = 0; r < 4; r++) w1s[t + 128 * r] = W1[t + 128 * r];

    const int ii = t >> 4;     // 8 i-groups
    const int hp = t & 15;     // h pairs {hp,hp+32} and {hp+16,hp+48}

    const int il = t >> 1, q = t & 1;
    const float4* src = reinterpret_cast<const float4*>(edge)
                        + ((ULL)(b * NN) * NN + j) * 2 + q;   // +512 per i

    float4 v = src[(ULL)il * 512];
    {
        float* d = &es[0][il * 18 + q * 8];
        *(float2*)&d[0] = make_float2(v.x, v.x);
        *(float2*)&d[2] = make_float2(v.y, v.y);
        *(float2*)&d[4] = make_float2(v.z, v.z);
        *(float2*)&d[6] = make_float2(v.w, v.w);
    }
    __syncthreads();   // w1s + hsum + chunk0 ready

    ULL w12[2][8], b2i[2];
    #pragma unroll
    for (int p = 0; p < 2; p++) {
        const int h0 = hp + p * 16;
        b2i[p] = pack2(b1[h0], b1[h0 + 32]);
        #pragma unroll
        for (int f = 0; f < 8; f++)
            w12[p][f] = pack2(w1s[f * 64 + h0], w1s[f * 64 + h0 + 32]);
    }

    float a0 = 0.f, a1 = 0.f, a2 = 0.f, a3 = 0.f;

    #pragma unroll 1
    for (int c = 0; c < 4; c++) {
        float4 v2;
        if (c < 3) v2 = src[(ULL)((c + 1) * 64 + il) * 512];

        const float* eb = es[c & 1];
        #pragma unroll
        for (int s = 0; s < 8; s++) {
            const float* er = &eb[(ii * 8 + s) * 18];
            ULL e[8];
            #pragma unroll
            for (int f = 0; f < 8; f++) e[f] = *(const ULL*)&er[2 * f];

            ULL h0 = fma2(e[0], w12[0][0], b2i[0]);
            ULL h1 = fma2(e[0], w12[1][0], b2i[1]);
            #pragma unroll
            for (int f = 1; f < 8; f++) {
                h0 = fma2(e[f], w12[0][f], h0);
                h1 = fma2(e[f], w12[1][f], h1);
            }
            float lo, hi;
            unpack2(h0, lo, hi);
            a0 += fmaxf(lo, 0.f); a1 += fmaxf(hi, 0.f);
            unpack2(h1, lo, hi);
            a2 += fmaxf(lo, 0.f); a3 += fmaxf(hi, 0.f);
        }

        if (c < 3) {
            float* d = &es[(c + 1) & 1][il * 18 + q * 8];
            *(float2*)&d[0] = make_float2(v2.x, v2.x);
            *(float2*)&d[2] = make_float2(v2.y, v2.y);
            *(float2*)&d[4] = make_float2(v2.z, v2.z);
            *(float2*)&d[6] = make_float2(v2.w, v2.w);
        }
        __syncthreads();
    }

    // reduce over ii pairs via shfl, then 2-deep shared atomics
    a0 += __shfl_xor_sync(0xffffffffu, a0, 16);
    a1 += __shfl_xor_sync(0xffffffffu, a1, 16);
    a2 += __shfl_xor_sync(0xffffffffu, a2, 16);
    a3 += __shfl_xor_sync(0xffffffffu, a3, 16);
    if ((t & 16) == 0) {
        atomicAdd(&hsum[hp],      a0);
        atomicAdd(&hsum[hp + 32], a1);
        atomicAdd(&hsum[hp + 16], a2);
        atomicAdd(&hsum[hp + 48], a3);
    }
    if (t >= 64 && t < 80) xs[t - 64] = x[bx * 16 + (t - 64)];
    __syncthreads();
    if (t < 64) { float hv = hsum[t]; hs2[t] = pack2(hv, hv); }
    __syncthreads();

    // ---------------- Phase B: wsum = Hsum @ W2  (W2 via L1) ----------------
    {
        const int hh = t >> 6;       // h-half: h in [32hh, 32hh+32)
        const int tc = t & 63;       // float4 col group: cols 4tc..4tc+3
        const float4* w2p = reinterpret_cast<const float4*>(W2) + hh * 32 * 64 + tc;

        ULL acc0 = 0, acc1 = 0;
        #pragma unroll 4
        for (int h2 = 0; h2 < 32; h2++) {
            float4 w = w2p[(ULL)h2 * 64];
            ULL hv = hs2[hh * 32 + h2];
            acc0 = fma2(hv, pack2(w.x, w.y), acc0);
            acc1 = fma2(hv, pack2(w.z, w.w), acc1);
        }
        float l0, h0, l1, h1;
        unpack2(acc0, l0, h0); unpack2(acc1, l1, h1);
        *(float4*)&wpart[hh][4 * tc] = make_float4(l0, h0, l1, h1);
    }
    __syncthreads();

    if (t < 64) {
        float4 p = *(const float4*)&wpart[0][4 * t];
        float4 r = *(const float4*)&wpart[1][4 * t];
        float4 bb = reinterpret_cast<const float4*>(b2)[t];
        float4 rr = reinterpret_cast<const float4*>(root)[t];
        float4 w;
        w.x = p.x + r.x + 256.f * bb.x + rr.x;
        w.y = p.y + r.y + 256.f * bb.y + rr.y;
        w.z = p.z + r.z + 256.f * bb.z + rr.z;
        w.w = p.w + r.w + 256.f * bb.w + rr.w;
        *(float4*)&wsf[4 * t] = w;
    }
    __syncthreads();

    // ---------------- Phase C: out[d] = sum_c x[c] * wsf[c*16+d] ------------
    if (t < 16) {
        float o = 0.f;
        #pragma unroll
        for (int c = 0; c < 16; c++)
            o += xs[c] * wsf[c * 16 + t];
        out[bx * 16 + t] = o;
    }
}

extern "C" void kernel_launch(void* const* d_in, const int* in_sizes, int n_in,
                              void* d_out, int out_size) {
    const float* node_attr = (const float*)d_in[0];
    const float* edge_adj  = (const float*)d_in[1];
    const float* W1        = (const float*)d_in[2];
    const float* b1        = (const float*)d_in[3];
    const float* W2        = (const float*)d_in[4];
    const float* b2        = (const float*)d_in[5];
    const float* root      = (const float*)d_in[6];
    float* out = (float*)d_out;

    k_fused<<<1024, 128>>>(node_attr, edge_adj, W1, b1, W2, b2, root, out);
}

// round 5
// speedup vs baseline: 1.5559x; 1.5559x over previous
#include <cuda_runtime.h>
#include <cstdint>

typedef unsigned long long ULL;

__device__ __forceinline__ ULL pack2(float lo, float hi) {
    ULL r; asm("mov.b64 %0, {%1, %2};" : "=l"(r) : "f"(lo), "f"(hi)); return r;
}
__device__ __forceinline__ void unpack2(ULL v, float& lo, float& hi) {
    asm("mov.b64 {%0, %1}, %2;" : "=f"(lo), "=f"(hi) : "l"(v));
}
__device__ __forceinline__ ULL fma2(ULL a, ULL b, ULL c) {
    ULL d; asm("fma.rn.f32x2 %0, %1, %2, %3;" : "=l"(d) : "l"(a), "l"(b), "l"(c)); return d;
}

#define NN 256

// partial Hsum: slot [half][node][h]
__device__ float g_Hs[2 * 1024 * 64];

// swizzled row offset (floats): rows r and r+8 land in disjoint bank windows
__device__ __forceinline__ int rowoff(int r) { return r * 20 + ((r >> 3) & 1) * 4; }

// ============================================================================
// K1: grid 2048 = (node, half). Each block: 128 i-rows (2 chunks of 64),
// Hsum_part[h] = sum_i relu(e[b,i,j,:]@W1 + b1), packed h-pair math,
// ReLU as 0.5*(v+|v|) so accumulators never unpack in the hot loop.
// ============================================================================
__global__ __launch_bounds__(128, 7)
void k_edge(const float* __restrict__ edge,
            const float* __restrict__ W1,
            const float* __restrict__ b1) {
    __shared__ float es[2][64 * 20 + 8];
    __shared__ float w1s[512];
    __shared__ float hsum[64];

    const int t    = threadIdx.x;
    const int bx   = blockIdx.x;
    const int node = bx >> 1;
    const int half = bx & 1;
    const int j    = node & 255;
    const int b    = node >> 8;

    if (t < 64) hsum[t] = 0.f;
    #pragma unroll
    for (int r = 0; r < 4; r++) w1s[t + 128 * r] = W1[t + 128 * r];

    const int ii = t >> 4;     // 8 i-groups of 8 rows
    const int hp = t & 15;     // h pairs {hp,hp+32}, {hp+16,hp+48}

    const int il = t >> 1, q = t & 1;
    const float4* src = reinterpret_cast<const float4*>(edge)
                        + ((ULL)(b * NN) * NN + j) * 2 + q
                        + (ULL)(half * 128) * 512;          // +512 float4 per i

    float4 v0 = src[(ULL)il * 512];
    {   // stage chunk 0 (duplicated pairs)
        float* d = &es[0][rowoff(il) + q * 8];
        *(float2*)&d[0] = make_float2(v0.x, v0.x);
        *(float2*)&d[2] = make_float2(v0.y, v0.y);
        *(float2*)&d[4] = make_float2(v0.z, v0.z);
        *(float2*)&d[6] = make_float2(v0.w, v0.w);
    }
    float4 v1 = src[(ULL)(64 + il) * 512];   // prefetch chunk 1
    __syncthreads();                          // chunk0 + w1s + hsum ready

    ULL w12[2][8], b2i[2];
    #pragma unroll
    for (int p = 0; p < 2; p++) {
        const int h0 = hp + p * 16;
        b2i[p] = pack2(b1[h0], b1[h0 + 32]);
        #pragma unroll
        for (int f = 0; f < 8; f++)
            w12[p][f] = pack2(w1s[f * 64 + h0], w1s[f * 64 + h0 + 32]);
    }

    const ULL HMASK = 0x7FFFFFFF7FFFFFFFULL;
    const ULL HALF2 = pack2(0.5f, 0.5f);
    ULL acc0 = pack2(0.f, 0.f), acc1 = acc0;

    #pragma unroll 1
    for (int c = 0; c < 2; c++) {
        const float* eb = es[c];
        #pragma unroll
        for (int s = 0; s < 8; s++) {
            const ULL* ep = (const ULL*)&eb[rowoff(ii * 8 + s)];
            ULL e0 = ep[0], e1 = ep[1], e2 = ep[2], e3 = ep[3];
            ULL e4 = ep[4], e5 = ep[5], e6 = ep[6], e7 = ep[7];

            ULL h0 = fma2(e0, w12[0][0], b2i[0]);
            ULL h1 = fma2(e0, w12[1][0], b2i[1]);
            h0 = fma2(e1, w12[0][1], h0);  h1 = fma2(e1, w12[1][1], h1);
            h0 = fma2(e2, w12[0][2], h0);  h1 = fma2(e2, w12[1][2], h1);
            h0 = fma2(e3, w12[0][3], h0);  h1 = fma2(e3, w12[1][3], h1);
            h0 = fma2(e4, w12[0][4], h0);  h1 = fma2(e4, w12[1][4], h1);
            h0 = fma2(e5, w12[0][5], h0);  h1 = fma2(e5, w12[1][5], h1);
            h0 = fma2(e6, w12[0][6], h0);  h1 = fma2(e6, w12[1][6], h1);
            h0 = fma2(e7, w12[0][7], h0);  h1 = fma2(e7, w12[1][7], h1);

            ULL a0 = h0 & HMASK;           // |h| per packed lane (alu pipe)
            ULL a1 = h1 & HMASK;
            acc0 = fma2(h0, HALF2, acc0);
            acc0 = fma2(a0, HALF2, acc0);
            acc1 = fma2(h1, HALF2, acc1);
            acc1 = fma2(a1, HALF2, acc1);
        }

        if (c == 0) {   // stage chunk 1 into the other buffer
            float* d = &es[1][rowoff(il) + q * 8];
            *(float2*)&d[0] = make_float2(v1.x, v1.x);
            *(float2*)&d[2] = make_float2(v1.y, v1.y);
            *(float2*)&d[4] = make_float2(v1.z, v1.z);
            *(float2*)&d[6] = make_float2(v1.w, v1.w);
            __syncthreads();
        }
    }

    float a0, a1, a2, a3;
    unpack2(acc0, a0, a1);     // h = hp, hp+32
    unpack2(acc1, a2, a3);     // h = hp+16, hp+48
    a0 += __shfl_xor_sync(0xffffffffu, a0, 16);
    a1 += __shfl_xor_sync(0xffffffffu, a1, 16);
    a2 += __shfl_xor_sync(0xffffffffu, a2, 16);
    a3 += __shfl_xor_sync(0xffffffffu, a3, 16);
    if ((t & 16) == 0) {
        atomicAdd(&hsum[hp],      a0);
        atomicAdd(&hsum[hp + 32], a1);
        atomicAdd(&hsum[hp + 16], a2);
        atomicAdd(&hsum[hp + 48], a3);
    }
    __syncthreads();
    if (t < 64) g_Hs[(half * 1024 + node) * 64 + t] = hsum[t];
}

// ============================================================================
// K2: one block per node, 128 threads. Merge the two Hsum halves, multiply by
// W2 (coalesced gmem reads, L1-hot across 7 blocks/SM), fold 256*b2+root,
// contract with x.
// ============================================================================
__global__ __launch_bounds__(128)
void k_node(const float* __restrict__ x,
            const float* __restrict__ W2,
            const float* __restrict__ b2,
            const float* __restrict__ root,
            float* __restrict__ out) {
    __shared__ ULL   hs2[64];
    __shared__ float wsf[256];
    __shared__ float xs[16];

    const int t    = threadIdx.x;
    const int node = blockIdx.x;

    if (t < 64) {
        float hv = g_Hs[node * 64 + t] + g_Hs[(1024 + node) * 64 + t];
        hs2[t] = pack2(hv, hv);
    }
    if (t >= 64 && t < 80) xs[t - 64] = x[node * 16 + (t - 64)];
    __syncthreads();

    // thread t owns output cols {2t, 2t+1} of the 256-wide wsum
    const ULL* w2p = reinterpret_cast<const ULL*>(W2) + t;
    ULL acc = pack2(0.f, 0.f);
    #pragma unroll 8
    for (int h = 0; h < 64; h++)
        acc = fma2(hs2[h], w2p[(ULL)h * 128], acc);

    float lo, hi; unpack2(acc, lo, hi);
    wsf[2 * t]     = lo + 256.f * b2[2 * t]     + root[2 * t];
    wsf[2 * t + 1] = hi + 256.f * b2[2 * t + 1] + root[2 * t + 1];
    __syncthreads();

    if (t < 16) {
        float o = 0.f;
        #pragma unroll
        for (int c = 0; c < 16; c++)
            o += xs[c] * wsf[c * 16 + t];
        out[node * 16 + t] = o;
    }
}

extern "C" void kernel_launch(void* const* d_in, const int* in_sizes, int n_in,
                              void* d_out, int out_size) {
    const float* node_attr = (const float*)d_in[0];
    const float* edge_adj  = (const float*)d_in[1];
    const float* W1        = (const float*)d_in[2];
    const float* b1        = (const float*)d_in[3];
    const float* W2        = (const float*)d_in[4];
    const float* b2        = (const float*)d_in[5];
    const float* root      = (const float*)d_in[6];
    float* out = (float*)d_out;

    k_edge<<<2048, 128>>>(edge_adj, W1, b1);
    k_node<<<1024, 128>>>(node_attr, W2, b2, root, out);
}

// round 6
// speedup vs baseline: 1.7038x; 1.0951x over previous
#include <cuda_runtime.h>
#include <cstdint>

typedef unsigned long long ULL;

__device__ __forceinline__ ULL pack2(float lo, float hi) {
    ULL r; asm("mov.b64 %0, {%1, %2};" : "=l"(r) : "f"(lo), "f"(hi)); return r;
}
__device__ __forceinline__ void unpack2(ULL v, float& lo, float& hi) {
    asm("mov.b64 {%0, %1}, %2;" : "=f"(lo), "=f"(hi) : "l"(v));
}
__device__ __forceinline__ ULL fma2(ULL a, ULL b, ULL c) {
    ULL d; asm("fma.rn.f32x2 %0, %1, %2, %3;" : "=l"(d) : "l"(a), "l"(b), "l"(c)); return d;
}

#define NN 256

// partial Hsum: slot [half][node][h]
__device__ float g_Hs[2 * 1024 * 64];

// swizzled row offset (floats): rows r and r+8 land in disjoint bank windows
__device__ __forceinline__ int rowoff(int r) { return r * 20 + ((r >> 3) & 1) * 4; }

// ============================================================================
// K1 (unchanged from R5): grid 2048 = (node, half). 128 i-rows per block.
// ============================================================================
__global__ __launch_bounds__(128, 7)
void k_edge(const float* __restrict__ edge,
            const float* __restrict__ W1,
            const float* __restrict__ b1) {
    __shared__ float es[2][64 * 20 + 8];
    __shared__ float w1s[512];
    __shared__ float hsum[64];

    const int t    = threadIdx.x;
    const int bx   = blockIdx.x;
    const int node = bx >> 1;
    const int half = bx & 1;
    const int j    = node & 255;
    const int b    = node >> 8;

    if (t < 64) hsum[t] = 0.f;
    #pragma unroll
    for (int r = 0; r < 4; r++) w1s[t + 128 * r] = W1[t + 128 * r];

    const int ii = t >> 4;
    const int hp = t & 15;

    const int il = t >> 1, q = t & 1;
    const float4* src = reinterpret_cast<const float4*>(edge)
                        + ((ULL)(b * NN) * NN + j) * 2 + q
                        + (ULL)(half * 128) * 512;

    float4 v0 = src[(ULL)il * 512];
    {
        float* d = &es[0][rowoff(il) + q * 8];
        *(float2*)&d[0] = make_float2(v0.x, v0.x);
        *(float2*)&d[2] = make_float2(v0.y, v0.y);
        *(float2*)&d[4] = make_float2(v0.z, v0.z);
        *(float2*)&d[6] = make_float2(v0.w, v0.w);
    }
    float4 v1 = src[(ULL)(64 + il) * 512];
    __syncthreads();

    ULL w12[2][8], b2i[2];
    #pragma unroll
    for (int p = 0; p < 2; p++) {
        const int h0 = hp + p * 16;
        b2i[p] = pack2(b1[h0], b1[h0 + 32]);
        #pragma unroll
        for (int f = 0; f < 8; f++)
            w12[p][f] = pack2(w1s[f * 64 + h0], w1s[f * 64 + h0 + 32]);
    }

    const ULL HMASK = 0x7FFFFFFF7FFFFFFFULL;
    const ULL HALF2 = pack2(0.5f, 0.5f);
    ULL acc0 = pack2(0.f, 0.f), acc1 = acc0;

    #pragma unroll 1
    for (int c = 0; c < 2; c++) {
        const float* eb = es[c];
        #pragma unroll
        for (int s = 0; s < 8; s++) {
            const ULL* ep = (const ULL*)&eb[rowoff(ii * 8 + s)];
            ULL e0 = ep[0], e1 = ep[1], e2 = ep[2], e3 = ep[3];
            ULL e4 = ep[4], e5 = ep[5], e6 = ep[6], e7 = ep[7];

            ULL h0 = fma2(e0, w12[0][0], b2i[0]);
            ULL h1 = fma2(e0, w12[1][0], b2i[1]);
            h0 = fma2(e1, w12[0][1], h0);  h1 = fma2(e1, w12[1][1], h1);
            h0 = fma2(e2, w12[0][2], h0);  h1 = fma2(e2, w12[1][2], h1);
            h0 = fma2(e3, w12[0][3], h0);  h1 = fma2(e3, w12[1][3], h1);
            h0 = fma2(e4, w12[0][4], h0);  h1 = fma2(e4, w12[1][4], h1);
            h0 = fma2(e5, w12[0][5], h0);  h1 = fma2(e5, w12[1][5], h1);
            h0 = fma2(e6, w12[0][6], h0);  h1 = fma2(e6, w12[1][6], h1);
            h0 = fma2(e7, w12[0][7], h0);  h1 = fma2(e7, w12[1][7], h1);

            ULL a0 = h0 & HMASK;
            ULL a1 = h1 & HMASK;
            acc0 = fma2(h0, HALF2, acc0);
            acc0 = fma2(a0, HALF2, acc0);
            acc1 = fma2(h1, HALF2, acc1);
            acc1 = fma2(a1, HALF2, acc1);
        }

        if (c == 0) {
            float* d = &es[1][rowoff(il) + q * 8];
            *(float2*)&d[0] = make_float2(v1.x, v1.x);
            *(float2*)&d[2] = make_float2(v1.y, v1.y);
            *(float2*)&d[4] = make_float2(v1.z, v1.z);
            *(float2*)&d[6] = make_float2(v1.w, v1.w);
            __syncthreads();
        }
    }

    float a0, a1, a2, a3;
    unpack2(acc0, a0, a1);
    unpack2(acc1, a2, a3);
    a0 += __shfl_xor_sync(0xffffffffu, a0, 16);
    a1 += __shfl_xor_sync(0xffffffffu, a1, 16);
    a2 += __shfl_xor_sync(0xffffffffu, a2, 16);
    a3 += __shfl_xor_sync(0xffffffffu, a3, 16);
    if ((t & 16) == 0) {
        atomicAdd(&hsum[hp],      a0);
        atomicAdd(&hsum[hp + 32], a1);
        atomicAdd(&hsum[hp + 16], a2);
        atomicAdd(&hsum[hp + 48], a3);
    }
    __syncthreads();
    if (t < 64) g_Hs[(half * 1024 + node) * 64 + t] = hsum[t];
}

// ============================================================================
// K2: grid 256 x 256 threads, 4 nodes/block.
// Thread = (colpair cp, h-half ph). W2 slice (32 ULL) preloaded into REGISTERS
// with one batched LDG burst; 4 independent 32-deep fma2 chains (one/node)
// from broadcast-LDS Hsum. SMEM combine of h-halves, then x-contraction.
// ============================================================================
__global__ __launch_bounds__(256, 2)
void k_node(const float* __restrict__ x,
            const float* __restrict__ W2,
            const float* __restrict__ b2,
            const float* __restrict__ root,
            float* __restrict__ out) {
    __shared__ ULL   hs2[4 * 64];     // [node][h] splatted
    __shared__ float wpart[4 * 256];  // ph==0 partials
    __shared__ float wsf[4 * 256];    // combined wsum + rb
    __shared__ float rb[256];
    __shared__ float xs[64];

    const int t     = threadIdx.x;
    const int node0 = blockIdx.x * 4;
    const int cp    = t & 127;        // colpair: cols {2cp, 2cp+1}
    const int ph    = t >> 7;         // h-half

    // stage Hsum (merge halves, splat), rb, x
    {
        float hv = g_Hs[node0 * 64 + t] + g_Hs[1024 * 64 + node0 * 64 + t];
        hs2[t] = pack2(hv, hv);
    }
    rb[t] = 256.f * b2[t] + root[t];
    if (t < 64) xs[t] = x[node0 * 16 + t];

    // preload W2 slice into registers: h = ph*32 + k, cols {2cp,2cp+1}
    ULL w2r[32];
    {
        const ULL* w2g = reinterpret_cast<const ULL*>(W2) + (ULL)(ph * 32) * 128 + cp;
        #pragma unroll
        for (int k = 0; k < 32; k++) w2r[k] = w2g[(ULL)k * 128];
    }
    __syncthreads();

    ULL acc[4];
    #pragma unroll
    for (int n = 0; n < 4; n++) acc[n] = pack2(0.f, 0.f);

    #pragma unroll
    for (int k = 0; k < 32; k++) {
        const ULL w = w2r[k];
        const int hh = ph * 32 + k;
        acc[0] = fma2(hs2[0 * 64 + hh], w, acc[0]);
        acc[1] = fma2(hs2[1 * 64 + hh], w, acc[1]);
        acc[2] = fma2(hs2[2 * 64 + hh], w, acc[2]);
        acc[3] = fma2(hs2[3 * 64 + hh], w, acc[3]);
    }

    if (ph == 0) {
        #pragma unroll
        for (int n = 0; n < 4; n++) {
            float lo, hi; unpack2(acc[n], lo, hi);
            wpart[n * 256 + 2 * cp]     = lo;
            wpart[n * 256 + 2 * cp + 1] = hi;
        }
    }
    __syncthreads();

    if (ph == 1) {
        #pragma unroll
        for (int n = 0; n < 4; n++) {
            float lo, hi; unpack2(acc[n], lo, hi);
            wsf[n * 256 + 2 * cp]     = lo + wpart[n * 256 + 2 * cp]     + rb[2 * cp];
            wsf[n * 256 + 2 * cp + 1] = hi + wpart[n * 256 + 2 * cp + 1] + rb[2 * cp + 1];
        }
    }
    __syncthreads();

    // x-contraction: 64 threads = 4 nodes x 16 d
    if (t < 64) {
        const int n = t >> 4, d = t & 15;
        float o = 0.f;
        #pragma unroll
        for (int c = 0; c < 16; c++)
            o += xs[n * 16 + c] * wsf[n * 256 + c * 16 + d];
        out[(node0 + n) * 16 + d] = o;
    }
}

extern "C" void kernel_launch(void* const* d_in, const int* in_sizes, int n_in,
                              void* d_out, int out_size) {
    const float* node_attr = (const float*)d_in[0];
    const float* edge_adj  = (const float*)d_in[1];
    const float* W1        = (const float*)d_in[2];
    const float* b1        = (const float*)d_in[3];
    const float* W2        = (const float*)d_in[4];
    const float* b2        = (const float*)d_in[5];
    const float* root      = (const float*)d_in[6];
    float* out = (float*)d_out;

    k_edge<<<2048, 128>>>(edge_adj, W1, b1);
    k_node<<<256, 256>>>(node_attr, W2, b2, root, out);
}